// round 1
// baseline (speedup 1.0000x reference)
#include <cuda_runtime.h>
#include <cstdint>

#define B_   16
#define T_   4096
#define DIM_ 256
#define H_   128
#define G3   384
#define BT   65536   // B_*T_

// Scratch: xg[d][bt][384] and two layer-activation ping-pong buffers.
__device__ float g_xg[2ull * BT * G3];          // ~201 MB
__device__ float g_buf[2][(size_t)BT * DIM_];   // 2 x 64 MB

typedef unsigned long long ull;

__device__ __forceinline__ ull ffma2(ull a, ull b, ull c) {
    ull d;
    asm("fma.rn.f32x2 %0, %1, %2, %3;" : "=l"(d) : "l"(a), "l"(b), "l"(c));
    return d;
}
__device__ __forceinline__ ull fpack2(float lo, float hi) {
    ull r;
    asm("mov.b64 %0, {%1, %2};" : "=l"(r) : "f"(lo), "f"(hi));
    return r;
}
__device__ __forceinline__ float2 funpack(ull v) {
    float2 r;
    asm("mov.b64 {%0, %1}, %2;" : "=f"(r.x), "=f"(r.y) : "l"(v));
    return r;
}
__device__ __forceinline__ float sigmoidf_fast(float x) {
    return __fdividef(1.0f, 1.0f + __expf(-x));
}
__device__ __forceinline__ float tanhf_fast(float x) {
    return __fdividef(2.0f, 1.0f + __expf(-2.0f * x)) - 1.0f;
}

// ---------------------------------------------------------------------------
// GEMM: xg[d][bt][c] = sum_k X[bt][k] * Wi[layer][d][k][c]
// Tiles: BM=64, BN=64, BK=16. 256 threads, 4x4 micro-tile, packed f32x2 FMA.
// M=65536, N=384, K=256 all divide evenly -> no bounds checks.
// ---------------------------------------------------------------------------
__global__ void __launch_bounds__(256) gemm_xg(const float* __restrict__ xext,
                                               const float* __restrict__ Wi,
                                               int layer) {
    const int d = blockIdx.z;
    const float* __restrict__ X = (layer == 0) ? xext : g_buf[layer - 1];
    const float* __restrict__ W = Wi + (size_t)(layer * 2 + d) * DIM_ * G3;
    float* __restrict__ C = g_xg + (size_t)d * BT * G3;

    const int m0 = blockIdx.y * 64;
    const int n0 = blockIdx.x * 64;

    __shared__ __align__(16) float As[16][72];   // [k][m], padded
    __shared__ __align__(16) ull   Bsd[16][64];  // B pre-duplicated into both f32x2 halves

    const int tid = threadIdx.x;
    const int tx = tid & 15, ty = tid >> 4;
    const int arow = tid >> 2, akq = (tid & 3) * 4;

    ull acc[2][4];
#pragma unroll
    for (int p = 0; p < 2; p++)
#pragma unroll
        for (int n = 0; n < 4; n++) acc[p][n] = 0ull;

#pragma unroll 1
    for (int k0 = 0; k0 < DIM_; k0 += 16) {
        float4 av = *(const float4*)(X + (size_t)(m0 + arow) * DIM_ + k0 + akq);
        As[akq + 0][arow] = av.x;
        As[akq + 1][arow] = av.y;
        As[akq + 2][arow] = av.z;
        As[akq + 3][arow] = av.w;
        float4 bv = *(const float4*)(W + (size_t)(k0 + ty) * G3 + n0 + tx * 4);
        Bsd[ty][tx * 4 + 0] = fpack2(bv.x, bv.x);
        Bsd[ty][tx * 4 + 1] = fpack2(bv.y, bv.y);
        Bsd[ty][tx * 4 + 2] = fpack2(bv.z, bv.z);
        Bsd[ty][tx * 4 + 3] = fpack2(bv.w, bv.w);
        __syncthreads();
#pragma unroll
        for (int k = 0; k < 16; k++) {
            ulonglong2 a2 = *(const ulonglong2*)&As[k][ty * 4];   // rows (0,1),(2,3)
            ulonglong2 bA = *(const ulonglong2*)&Bsd[k][tx * 4];      // cols 0,1 (dup)
            ulonglong2 bB = *(const ulonglong2*)&Bsd[k][tx * 4 + 2];  // cols 2,3 (dup)
            acc[0][0] = ffma2(a2.x, bA.x, acc[0][0]);
            acc[0][1] = ffma2(a2.x, bA.y, acc[0][1]);
            acc[0][2] = ffma2(a2.x, bB.x, acc[0][2]);
            acc[0][3] = ffma2(a2.x, bB.y, acc[0][3]);
            acc[1][0] = ffma2(a2.y, bA.x, acc[1][0]);
            acc[1][1] = ffma2(a2.y, bA.y, acc[1][1]);
            acc[1][2] = ffma2(a2.y, bB.x, acc[1][2]);
            acc[1][3] = ffma2(a2.y, bB.y, acc[1][3]);
        }
        __syncthreads();
    }

#pragma unroll
    for (int p = 0; p < 2; p++) {
        float2 c0v = funpack(acc[p][0]);
        float2 c1v = funpack(acc[p][1]);
        float2 c2v = funpack(acc[p][2]);
        float2 c3v = funpack(acc[p][3]);
        int r0 = m0 + ty * 4 + p * 2;
        float4 lo = make_float4(c0v.x, c1v.x, c2v.x, c3v.x);
        float4 hi = make_float4(c0v.y, c1v.y, c2v.y, c3v.y);
        *(float4*)(C + (size_t)r0 * G3 + n0 + tx * 4) = lo;
        *(float4*)(C + (size_t)(r0 + 1) * G3 + n0 + tx * 4) = hi;
    }
}

// ---------------------------------------------------------------------------
// Recurrence: one CTA per (batch, direction). 512 threads.
// Thread (c0 = tid&127, s = tid>>7) owns rows [s*32, s*32+32) of columns
// {c0, 128+c0, 256+c0} of Wh, held in 96 registers as 48 f32x2 pairs.
// Per step: 48 FMA2/thread (FMA-pipe floor 384 cyc), smem reduce over s,
// gate epilogue on threads 0..127, 2 barriers.
// ---------------------------------------------------------------------------
__global__ void __launch_bounds__(512, 1) rnn_layer(const float* __restrict__ Wh,
                                                    const float* __restrict__ bh,
                                                    int layer,
                                                    float* __restrict__ Yext) {
    const int b = blockIdx.x & 15;
    const int d = blockIdx.x >> 4;
    float* __restrict__ Y = (layer == 2) ? Yext : g_buf[layer];
    const float* __restrict__ W = Wh + (size_t)(layer * 2 + d) * H_ * G3;
    const float* __restrict__ bhp = bh + (size_t)(layer * 2 + d) * G3;
    const float* __restrict__ xg = g_xg + ((size_t)d * BT + (size_t)b * T_) * G3;

    const int tid = threadIdx.x;
    const int c0 = tid & 127;
    const int s = tid >> 7;  // 0..3

    __shared__ __align__(16) float h_s[H_];
    __shared__ float part[3][4][H_];
    __shared__ float b_s[G3];

    // Load this thread's Wh slice into registers (f32x2-packed along k).
    ull whr[16], whz[16], whn[16];
    {
        const float* Wr = W + c0;
        const float* Wz = W + 128 + c0;
        const float* Wn = W + 256 + c0;
#pragma unroll
        for (int j = 0; j < 16; j++) {
            int k = s * 32 + 2 * j;
            whr[j] = fpack2(Wr[(size_t)k * G3], Wr[(size_t)(k + 1) * G3]);
            whz[j] = fpack2(Wz[(size_t)k * G3], Wz[(size_t)(k + 1) * G3]);
            whn[j] = fpack2(Wn[(size_t)k * G3], Wn[(size_t)(k + 1) * G3]);
        }
    }
    if (tid < H_) h_s[tid] = 0.0f;
    if (tid < G3) b_s[tid] = bhp[tid];
    __syncthreads();

    const bool phaseB = (tid < 128);
    const int step_dir = d ? -1 : 1;
    int tt = d ? (T_ - 1) : 0;

    float xr = 0.f, xz = 0.f, xn = 0.f;
    if (phaseB) {
        const float* p = xg + (size_t)tt * G3;
        xr = p[c0];
        xz = p[128 + c0];
        xn = p[256 + c0];
    }
    float* yrow = Y + (size_t)b * T_ * DIM_ + d * H_;
    const ulonglong2* hp = (const ulonglong2*)&h_s[s * 32];

#pragma unroll 1
    for (int t = 0; t < T_; t++) {
        // Prefetch next timestep's xg (hides DRAM latency behind the matvec).
        float nxr = 0.f, nxz = 0.f, nxn = 0.f;
        if (phaseB && (t + 1 < T_)) {
            const float* p = xg + (size_t)(tt + step_dir) * G3;
            nxr = p[c0];
            nxz = p[128 + c0];
            nxn = p[256 + c0];
        }

        // h @ Wh partials for this thread's (row-range, 3 columns).
        ull ar0 = 0, ar1 = 0, az0 = 0, az1 = 0, an0 = 0, an1 = 0;
#pragma unroll
        for (int j = 0; j < 8; j++) {
            ulonglong2 hv = hp[j];  // 4 h values (broadcast LDS.128)
            ar0 = ffma2(whr[2 * j], hv.x, ar0);
            ar1 = ffma2(whr[2 * j + 1], hv.y, ar1);
            az0 = ffma2(whz[2 * j], hv.x, az0);
            az1 = ffma2(whz[2 * j + 1], hv.y, az1);
            an0 = ffma2(whn[2 * j], hv.x, an0);
            an1 = ffma2(whn[2 * j + 1], hv.y, an1);
        }
        {
            float2 a = funpack(ar0), bb = funpack(ar1);
            part[0][s][c0] = (a.x + a.y) + (bb.x + bb.y);
            float2 c = funpack(az0), dd = funpack(az1);
            part[1][s][c0] = (c.x + c.y) + (dd.x + dd.y);
            float2 e = funpack(an0), f = funpack(an1);
            part[2][s][c0] = (e.x + e.y) + (f.x + f.y);
        }
        __syncthreads();

        if (phaseB) {
            float dr = (part[0][0][c0] + part[0][1][c0]) + (part[0][2][c0] + part[0][3][c0]);
            float dz = (part[1][0][c0] + part[1][1][c0]) + (part[1][2][c0] + part[1][3][c0]);
            float dn = (part[2][0][c0] + part[2][1][c0]) + (part[2][2][c0] + part[2][3][c0]);
            float r = sigmoidf_fast(xr + dr + b_s[c0]);
            float z = sigmoidf_fast(xz + dz + b_s[128 + c0]);
            float n = tanhf_fast(xn + r * (dn + b_s[256 + c0]));
            float hold = h_s[c0];
            float hnew = (1.0f - z) * n + z * hold;
            h_s[c0] = hnew;
            yrow[(size_t)tt * DIM_ + c0] = hnew;
            xr = nxr;
            xz = nxz;
            xn = nxn;
        }
        __syncthreads();
        tt += step_dir;
    }
}

// ---------------------------------------------------------------------------
extern "C" void kernel_launch(void* const* d_in, const int* in_sizes, int n_in,
                              void* d_out, int out_size) {
    (void)in_sizes;
    (void)n_in;
    (void)out_size;
    const float* x = (const float*)d_in[0];    // [16,4096,256]
    const float* Wi = (const float*)d_in[1];   // [3,2,256,384]
    const float* Wh = (const float*)d_in[2];   // [3,2,128,384]
    const float* bh = (const float*)d_in[3];   // [3,2,384]
    float* out = (float*)d_out;                // [16,4096,256]

    dim3 ggrid(G3 / 64, BT / 64, 2);  // (6, 1024, 2)
    for (int l = 0; l < 3; l++) {
        gemm_xg<<<ggrid, 256>>>(x, Wi, l);
        rnn_layer<<<32, 512>>>(Wh, bh, l, out);
    }
}

// round 2
// speedup vs baseline: 1.4372x; 1.4372x over previous
#include <cuda_runtime.h>
#include <cstdint>

#define B_   16
#define T_   4096
#define DIM_ 256
#define H_   128
#define G3   384
#define BT   65536   // B_*T_

// Scratch: xg[d][bt][384] and two layer-activation ping-pong buffers.
__device__ float g_xg[2ull * BT * G3];          // ~201 MB
__device__ float g_buf[2][(size_t)BT * DIM_];   // 2 x 64 MB

typedef unsigned long long ull;

__device__ __forceinline__ ull ffma2(ull a, ull b, ull c) {
    ull d;
    asm("fma.rn.f32x2 %0, %1, %2, %3;" : "=l"(d) : "l"(a), "l"(b), "l"(c));
    return d;
}
__device__ __forceinline__ ull fpack2(float lo, float hi) {
    ull r;
    asm("mov.b64 %0, {%1, %2};" : "=l"(r) : "f"(lo), "f"(hi));
    return r;
}
__device__ __forceinline__ float2 funpack(ull v) {
    float2 r;
    asm("mov.b64 {%0, %1}, %2;" : "=f"(r.x), "=f"(r.y) : "l"(v));
    return r;
}
__device__ __forceinline__ float sigmoidf_fast(float x) {
    return __fdividef(1.0f, 1.0f + __expf(-x));
}
__device__ __forceinline__ float tanhf_fast(float x) {
    return __fdividef(2.0f, 1.0f + __expf(-2.0f * x)) - 1.0f;
}

// ---------------------------------------------------------------------------
// GEMM: xg[d][bt][c] = sum_k X[bt][k] * Wi[layer][d][k][c]
// 128x128 CTA tile, BK=16, 256 threads, 8x8 scalar micro-tile (FMA-bound:
// 64B LDS per 64 FFMA). Register-prefetched k-blocks. 2 CTAs/SM.
// M=65536, N=384, K=256 divide evenly -> no bounds checks.
// ---------------------------------------------------------------------------
__global__ void __launch_bounds__(256, 2) gemm_xg(const float* __restrict__ xext,
                                                  const float* __restrict__ Wi,
                                                  int layer) {
    const int d = blockIdx.z;
    const float* __restrict__ X = (layer == 0) ? xext : g_buf[layer - 1];
    const float* __restrict__ W = Wi + (size_t)(layer * 2 + d) * DIM_ * G3;
    float* __restrict__ C = g_xg + (size_t)d * BT * G3;

    const int m0 = blockIdx.y * 128;
    const int n0 = blockIdx.x * 128;

    __shared__ __align__(16) float As[16][128];  // [k][m]
    __shared__ __align__(16) float Bs[16][128];  // [k][n]

    const int tid = threadIdx.x;
    // A fill: thread loads 8 contiguous k for one row, stores transposed.
    const int ar = tid >> 1;            // row 0..127
    const int akq = (tid & 1) * 8;      // k 0 or 8
    // B fill: thread loads 8 contiguous n for one k row.
    const int bk = tid >> 4;            // k 0..15
    const int bc = (tid & 15) * 8;      // n 0..120
    // Micro-tile: 16x16 thread grid, 8 rows x 8 cols each.
    const int ry = (tid >> 4) * 8;
    const int cx = (tid & 15) * 8;

    const float* Arow = X + (size_t)(m0 + ar) * DIM_ + akq;
    const float* Brow = W + (size_t)bk * G3 + n0 + bc;

    float acc[8][8];
#pragma unroll
    for (int i = 0; i < 8; i++)
#pragma unroll
        for (int j = 0; j < 8; j++) acc[i][j] = 0.0f;

    // Load first tile.
    float4 a0 = *(const float4*)(Arow + 0);
    float4 a1 = *(const float4*)(Arow + 4);
    float4 b0 = *(const float4*)(Brow + 0);
    float4 b1 = *(const float4*)(Brow + 4);

#pragma unroll 1
    for (int k0 = 0; k0 < DIM_; k0 += 16) {
        // Commit the prefetched tile to smem.
        As[akq + 0][ar] = a0.x; As[akq + 1][ar] = a0.y;
        As[akq + 2][ar] = a0.z; As[akq + 3][ar] = a0.w;
        As[akq + 4][ar] = a1.x; As[akq + 5][ar] = a1.y;
        As[akq + 6][ar] = a1.z; As[akq + 7][ar] = a1.w;
        *(float4*)&Bs[bk][bc] = b0;
        *(float4*)&Bs[bk][bc + 4] = b1;
        __syncthreads();

        // Prefetch next tile into registers (hidden under the FMA block).
        if (k0 + 16 < DIM_) {
            a0 = *(const float4*)(Arow + k0 + 16);
            a1 = *(const float4*)(Arow + k0 + 20);
            b0 = *(const float4*)(Brow + (size_t)(k0 + 16) * G3);
            b1 = *(const float4*)(Brow + (size_t)(k0 + 16) * G3 + 4);
        }

#pragma unroll
        for (int k = 0; k < 16; k++) {
            float4 av0 = *(const float4*)&As[k][ry];
            float4 av1 = *(const float4*)&As[k][ry + 4];
            float4 bv0 = *(const float4*)&Bs[k][cx];
            float4 bv1 = *(const float4*)&Bs[k][cx + 4];
            float a[8] = {av0.x, av0.y, av0.z, av0.w, av1.x, av1.y, av1.z, av1.w};
            float b[8] = {bv0.x, bv0.y, bv0.z, bv0.w, bv1.x, bv1.y, bv1.z, bv1.w};
#pragma unroll
            for (int i = 0; i < 8; i++)
#pragma unroll
                for (int j = 0; j < 8; j++) acc[i][j] = fmaf(a[i], b[j], acc[i][j]);
        }
        __syncthreads();
    }

#pragma unroll
    for (int i = 0; i < 8; i++) {
        float* crow = C + (size_t)(m0 + ry + i) * G3 + n0 + cx;
        *(float4*)(crow) = make_float4(acc[i][0], acc[i][1], acc[i][2], acc[i][3]);
        *(float4*)(crow + 4) = make_float4(acc[i][4], acc[i][5], acc[i][6], acc[i][7]);
    }
}

// ---------------------------------------------------------------------------
// Recurrence: one CTA per (batch, direction). 384 threads.
// Thread t owns FULL column t of Wh[128,384] in registers (128 floats as
// 64 f32x2 pairs) -> each thread computes a complete dot product, no partial
// reduction. Gates: threads 0-127 = r, 128-255 = z, 256-383 = n.
// r/z activations exchanged to the n-threads through smem inside the two
// per-step barriers. 384 threads -> 170-reg ceiling, no spills (~147 used).
// ---------------------------------------------------------------------------
__global__ void __launch_bounds__(384, 1) rnn_layer(const float* __restrict__ Wh,
                                                    const float* __restrict__ bh,
                                                    int layer,
                                                    float* __restrict__ Yext) {
    const int b = blockIdx.x & 15;
    const int d = blockIdx.x >> 4;
    float* __restrict__ Y = (layer == 2) ? Yext : g_buf[layer];
    const float* __restrict__ W = Wh + (size_t)(layer * 2 + d) * H_ * G3;
    const float* __restrict__ bhp = bh + (size_t)(layer * 2 + d) * G3;
    const float* __restrict__ xg = g_xg + ((size_t)d * BT + (size_t)b * T_) * G3;

    const int tid = threadIdx.x;
    const int c0 = tid & 127;
    const int gate = tid >> 7;  // 0=r, 1=z, 2=n

    __shared__ __align__(16) float h_s[H_];
    __shared__ float rr[H_];
    __shared__ float zz[H_];

    // Full column tid of Wh, packed f32x2 along k.
    ull w[64];
    {
        const float* Wc = W + tid;
#pragma unroll
        for (int j = 0; j < 64; j++)
            w[j] = fpack2(Wc[(size_t)(2 * j) * G3], Wc[(size_t)(2 * j + 1) * G3]);
    }
    const float bias = bhp[tid];

    if (tid < H_) h_s[tid] = 0.0f;
    __syncthreads();

    const int step_dir = d ? -1 : 1;
    int tt = d ? (T_ - 1) : 0;

    float xv = xg[(size_t)tt * G3 + tid];
    float* const yrow = Y + (size_t)b * T_ * DIM_ + d * H_;
    const ulonglong2* const hp = (const ulonglong2*)h_s;

#pragma unroll 1
    for (int t = 0; t < T_; t++) {
        // Prefetch next timestep's xg element (DRAM latency hidden by step).
        float nxv = 0.0f;
        if (t + 1 < T_) nxv = xg[(size_t)(tt + step_dir) * G3 + tid];

        // Full dot product: h . Wh[:, tid]  (32 broadcast LDS.128, 64 FFMA2).
        ull acc0 = 0, acc1 = 0;
#pragma unroll
        for (int j = 0; j < 32; j++) {
            ulonglong2 hv = hp[j];
            acc0 = ffma2(w[2 * j], hv.x, acc0);
            acc1 = ffma2(w[2 * j + 1], hv.y, acc1);
        }
        float2 lo = funpack(acc0), hi = funpack(acc1);
        float dot = (lo.x + lo.y) + (hi.x + hi.y);

        if (gate == 0) {
            rr[c0] = sigmoidf_fast(xv + dot + bias);
        } else if (gate == 1) {
            zz[c0] = sigmoidf_fast(xv + dot + bias);
        }
        __syncthreads();  // r,z published; all dots done

        if (gate == 2) {
            float r = rr[c0];
            float z = zz[c0];
            float hold = h_s[c0];
            float n = tanhf_fast(xv + r * (dot + bias));
            float hnew = (1.0f - z) * n + z * hold;
            h_s[c0] = hnew;
            yrow[(size_t)tt * DIM_ + c0] = hnew;
        }
        __syncthreads();  // new h visible to everyone

        xv = nxv;
        tt += step_dir;
    }
}

// ---------------------------------------------------------------------------
extern "C" void kernel_launch(void* const* d_in, const int* in_sizes, int n_in,
                              void* d_out, int out_size) {
    (void)in_sizes;
    (void)n_in;
    (void)out_size;
    const float* x = (const float*)d_in[0];    // [16,4096,256]
    const float* Wi = (const float*)d_in[1];   // [3,2,256,384]
    const float* Wh = (const float*)d_in[2];   // [3,2,128,384]
    const float* bh = (const float*)d_in[3];   // [3,2,384]
    float* out = (float*)d_out;                // [16,4096,256]

    dim3 ggrid(G3 / 128, BT / 128, 2);  // (3, 512, 2)
    for (int l = 0; l < 3; l++) {
        gemm_xg<<<ggrid, 256>>>(x, Wi, l);
        rnn_layer<<<32, 384>>>(Wh, bh, l, out);
    }
}

// round 3
// speedup vs baseline: 1.4844x; 1.0329x over previous
#include <cuda_runtime.h>
#include <cstdint>

#define B_   16
#define T_   4096
#define DIM_ 256
#define H_   128
#define G3   384
#define BT   65536   // B_*T_

// Scratch: xg[d][bt][384] and two layer-activation ping-pong buffers.
__device__ float g_xg[2ull * BT * G3];          // ~201 MB
__device__ float g_buf[2][(size_t)BT * DIM_];   // 2 x 64 MB

typedef unsigned long long ull;

__device__ __forceinline__ ull ffma2(ull a, ull b, ull c) {
    ull d;
    asm("fma.rn.f32x2 %0, %1, %2, %3;" : "=l"(d) : "l"(a), "l"(b), "l"(c));
    return d;
}
__device__ __forceinline__ ull fpack2(float lo, float hi) {
    ull r;
    asm("mov.b64 %0, {%1, %2};" : "=l"(r) : "f"(lo), "f"(hi));
    return r;
}
__device__ __forceinline__ float2 funpack(ull v) {
    float2 r;
    asm("mov.b64 {%0, %1}, %2;" : "=f"(r.x), "=f"(r.y) : "l"(v));
    return r;
}
__device__ __forceinline__ float sigmoidf_fast(float x) {
    return __fdividef(1.0f, 1.0f + __expf(-x));
}
__device__ __forceinline__ float tanhf_fast(float x) {
    return __fdividef(2.0f, 1.0f + __expf(-2.0f * x)) - 1.0f;
}

// ---------------------------------------------------------------------------
// GEMM: xg[d][bt][c] = sum_k X[bt][k] * Wi[layer][d][k][c]
// 128x128 CTA tile, BK=16, 256 threads. f32x2 micro-tile: 8 rows (4 f32x2
// pairs) x 8 cols per thread = 32 FFMA2/k. B is duplicated into both f32x2
// halves in smem; threads own STRIDED columns (tx + 16*j) so the 8 B reads
// per k are conflict-free LDS.64 (contiguous-col layout would be 8-way).
// ---------------------------------------------------------------------------
__global__ void __launch_bounds__(256, 2) gemm_xg(const float* __restrict__ xext,
                                                  const float* __restrict__ Wi,
                                                  int layer) {
    const int d = blockIdx.z;
    const float* __restrict__ X = (layer == 0) ? xext : g_buf[layer - 1];
    const float* __restrict__ W = Wi + (size_t)(layer * 2 + d) * DIM_ * G3;
    float* __restrict__ C = g_xg + (size_t)d * BT * G3;

    const int m0 = blockIdx.y * 128;
    const int n0 = blockIdx.x * 128;

    __shared__ __align__(16) float As[16][128];   // [k][m]
    __shared__ __align__(16) ull   Bsd[16][128];  // [k][n] duplicated (b,b)

    const int tid = threadIdx.x;
    // A fill: thread -> (row ar, k-octet akq), stores transposed.
    const int ar = tid >> 1;
    const int akq = (tid & 1) * 8;
    // B fill: warp wq fills k-rows wq and wq+8; lane lq covers cols 4lq..4lq+3.
    const int wq = tid >> 5;
    const int lq = tid & 31;
    // Compute mapping: 16x16 grid; 8 rows x 8 strided cols each.
    const int ty = tid >> 4, tx = tid & 15;
    const int ry = ty * 8;

    const float* Ap = X + (size_t)(m0 + ar) * DIM_ + akq;
    const float* Bp0 = W + (size_t)wq * G3 + n0 + 4 * lq;
    const float* Bp1 = W + (size_t)(wq + 8) * G3 + n0 + 4 * lq;

    ull acc[4][8];
#pragma unroll
    for (int i = 0; i < 4; i++)
#pragma unroll
        for (int j = 0; j < 8; j++) acc[i][j] = 0ull;

    float4 a0 = *(const float4*)(Ap);
    float4 a1 = *(const float4*)(Ap + 4);
    float4 b0 = *(const float4*)(Bp0);
    float4 b1 = *(const float4*)(Bp1);

#pragma unroll 1
    for (int k0 = 0; k0 < DIM_; k0 += 16) {
        As[akq + 0][ar] = a0.x; As[akq + 1][ar] = a0.y;
        As[akq + 2][ar] = a0.z; As[akq + 3][ar] = a0.w;
        As[akq + 4][ar] = a1.x; As[akq + 5][ar] = a1.y;
        As[akq + 6][ar] = a1.z; As[akq + 7][ar] = a1.w;
        {
            ulonglong2 p;
            p.x = fpack2(b0.x, b0.x); p.y = fpack2(b0.y, b0.y);
            *(ulonglong2*)&Bsd[wq][4 * lq] = p;
            p.x = fpack2(b0.z, b0.z); p.y = fpack2(b0.w, b0.w);
            *(ulonglong2*)&Bsd[wq][4 * lq + 2] = p;
            p.x = fpack2(b1.x, b1.x); p.y = fpack2(b1.y, b1.y);
            *(ulonglong2*)&Bsd[wq + 8][4 * lq] = p;
            p.x = fpack2(b1.z, b1.z); p.y = fpack2(b1.w, b1.w);
            *(ulonglong2*)&Bsd[wq + 8][4 * lq + 2] = p;
        }
        __syncthreads();

        if (k0 + 16 < DIM_) {
            a0 = *(const float4*)(Ap + k0 + 16);
            a1 = *(const float4*)(Ap + k0 + 20);
            b0 = *(const float4*)(Bp0 + (size_t)(k0 + 16) * G3);
            b1 = *(const float4*)(Bp1 + (size_t)(k0 + 16) * G3);
        }

#pragma unroll
        for (int k = 0; k < 16; k++) {
            ulonglong2 aA = *(const ulonglong2*)&As[k][ry];      // rows ry..ry+3
            ulonglong2 aB = *(const ulonglong2*)&As[k][ry + 4];  // rows ry+4..ry+7
            ull bb[8];
#pragma unroll
            for (int j = 0; j < 8; j++) bb[j] = Bsd[k][tx + 16 * j];
#pragma unroll
            for (int j = 0; j < 8; j++) {
                acc[0][j] = ffma2(aA.x, bb[j], acc[0][j]);
                acc[1][j] = ffma2(aA.y, bb[j], acc[1][j]);
                acc[2][j] = ffma2(aB.x, bb[j], acc[2][j]);
                acc[3][j] = ffma2(aB.y, bb[j], acc[3][j]);
            }
        }
        __syncthreads();
    }

#pragma unroll
    for (int i = 0; i < 4; i++) {
        float* c0p = C + (size_t)(m0 + ry + 2 * i) * G3 + n0 + tx;
        float* c1p = c0p + G3;
#pragma unroll
        for (int j = 0; j < 8; j++) {
            float2 v = funpack(acc[i][j]);
            c0p[16 * j] = v.x;
            c1p[16 * j] = v.y;
        }
    }
}

// ---------------------------------------------------------------------------
// Recurrence: one CTA per (batch, direction). 384 threads, thread t owns full
// column t of Wh (64 f32x2 regs). Manual 1-deep pipeline on the h loads so
// LDS latency is hidden; xg prefetch moved after the dot to free registers.
// Gates: 0-127=r, 128-255=z, 256-383=n; exchange via smem, 2 barriers/step.
// ---------------------------------------------------------------------------
__global__ void __launch_bounds__(384, 1) rnn_layer(const float* __restrict__ Wh,
                                                    const float* __restrict__ bh,
                                                    int layer,
                                                    float* __restrict__ Yext) {
    const int b = blockIdx.x & 15;
    const int d = blockIdx.x >> 4;
    float* __restrict__ Y = (layer == 2) ? Yext : g_buf[layer];
    const float* __restrict__ W = Wh + (size_t)(layer * 2 + d) * H_ * G3;
    const float* __restrict__ bhp = bh + (size_t)(layer * 2 + d) * G3;
    const float* __restrict__ xg = g_xg + ((size_t)d * BT + (size_t)b * T_) * G3;

    const int tid = threadIdx.x;
    const int c0 = tid & 127;
    const int gate = tid >> 7;  // 0=r, 1=z, 2=n

    __shared__ __align__(16) float h_s[H_];
    __shared__ float rr[H_];
    __shared__ float zz[H_];

    ull w[64];
    {
        const float* Wc = W + tid;
#pragma unroll
        for (int j = 0; j < 64; j++)
            w[j] = fpack2(Wc[(size_t)(2 * j) * G3], Wc[(size_t)(2 * j + 1) * G3]);
    }
    const float bias = bhp[tid];
    const float badd = (gate == 2) ? 0.0f : bias;  // fold bias into xr/xz

    if (tid < H_) h_s[tid] = 0.0f;
    __syncthreads();

    const int sd = d ? -1 : 1;
    const long xstep = (long)sd * G3;
    const long ystep = (long)sd * DIM_;
    const float* xp = xg + (d ? (size_t)(T_ - 1) * G3 : 0) + tid;
    float* yp = Y + (size_t)b * T_ * DIM_ + d * H_ + c0 +
                (d ? (size_t)(T_ - 1) * DIM_ : 0);

    float xv = *xp + badd;
    xp += xstep;

    const ulonglong2* const hp = (const ulonglong2*)h_s;

#pragma unroll 1
    for (int t = 0; t < T_; t++) {
        // Dot product h . Wh[:, tid] with 1-deep pipelined h loads.
        ull acc0 = 0, acc1 = 0;
        ulonglong2 hv = hp[0];
#pragma unroll
        for (int j = 0; j < 32; j++) {
            ulonglong2 hn = hp[(j + 1) & 31];
            acc0 = ffma2(w[2 * j], hv.x, acc0);
            acc1 = ffma2(w[2 * j + 1], hv.y, acc1);
            hv = hn;
        }
        float2 lo = funpack(acc0), hi = funpack(acc1);
        float dot = (lo.x + lo.y) + (hi.x + hi.y);

        // Prefetch next timestep's xg now (registers free, off critical path).
        // Unconditional: the one-past-the-end row stays inside g_xg (checked).
        float nxv = *xp + badd;
        xp += xstep;

        float hold = 0.0f, dn = 0.0f;
        if (gate == 0) {
            rr[c0] = sigmoidf_fast(xv + dot);
        } else if (gate == 1) {
            zz[c0] = sigmoidf_fast(xv + dot);
        } else {
            dn = dot + bias;      // pre-bar work for the n path
            hold = h_s[c0];
        }
        __syncthreads();  // r,z published

        if (gate == 2) {
            float r = rr[c0];
            float z = zz[c0];
            float n = tanhf_fast(fmaf(r, dn, xv));
            float hnew = fmaf(z, hold - n, n);
            h_s[c0] = hnew;
            *yp = hnew;
        }
        __syncthreads();  // new h visible

        xv = nxv;
        yp += ystep;
    }
}

// ---------------------------------------------------------------------------
extern "C" void kernel_launch(void* const* d_in, const int* in_sizes, int n_in,
                              void* d_out, int out_size) {
    (void)in_sizes;
    (void)n_in;
    (void)out_size;
    const float* x = (const float*)d_in[0];    // [16,4096,256]
    const float* Wi = (const float*)d_in[1];   // [3,2,256,384]
    const float* Wh = (const float*)d_in[2];   // [3,2,128,384]
    const float* bh = (const float*)d_in[3];   // [3,2,384]
    float* out = (float*)d_out;                // [16,4096,256]

    dim3 ggrid(G3 / 128, BT / 128, 2);  // (3, 512, 2)
    for (int l = 0; l < 3; l++) {
        gemm_xg<<<ggrid, 256>>>(x, Wi, l);
        rnn_layer<<<32, 384>>>(Wh, bh, l, out);
    }
}

// round 4
// speedup vs baseline: 1.6222x; 1.0928x over previous
#include <cuda_runtime.h>
#include <cstdint>

#define B_    16
#define T_    4096
#define DIM_  256
#define H_    128
#define G3    384
#define BT    65536   // B_*T_
#define CHUNK 128
#define NCHUNK 32     // T_/CHUNK
#define NMT   512     // BT/128 m-tiles
#define NNT   4       // 384/96 n-tiles
#define TICKETS (2*NMT*NNT)  // 4096 per layer

// Scratch: two xg buffers (layer parity), two activation buffers, sync state.
__device__ float g_xg[2][2ull * BT * G3];       // 2 x 201 MB
__device__ float g_buf[2][(size_t)BT * DIM_];   // 2 x 64 MB
__device__ int g_tileflag[3][2][NMT];           // n-tiles done per (l,d,mtile)
__device__ int g_prog[3][2][B_];                // rnn steps done per (l,d,b)
__device__ int g_ticket[3];                     // gemm work queue heads

typedef unsigned long long ull;

__device__ __forceinline__ ull ffma2(ull a, ull b, ull c) {
    ull d;
    asm("fma.rn.f32x2 %0, %1, %2, %3;" : "=l"(d) : "l"(a), "l"(b), "l"(c));
    return d;
}
__device__ __forceinline__ ull fpack2(float lo, float hi) {
    ull r;
    asm("mov.b64 %0, {%1, %2};" : "=l"(r) : "f"(lo), "f"(hi));
    return r;
}
__device__ __forceinline__ float2 funpack(ull v) {
    float2 r;
    asm("mov.b64 {%0, %1}, %2;" : "=f"(r.x), "=f"(r.y) : "l"(v));
    return r;
}
__device__ __forceinline__ float sigmoidf_fast(float x) {
    return __fdividef(1.0f, 1.0f + __expf(-x));
}
__device__ __forceinline__ float tanhf_fast(float x) {
    return __fdividef(2.0f, 1.0f + __expf(-2.0f * x)) - 1.0f;
}

__global__ void init_sync() {
    int i = blockIdx.x * blockDim.x + threadIdx.x;
    if (i < 3 * 2 * NMT) ((int*)g_tileflag)[i] = 0;
    if (i < 3 * 2 * B_) ((int*)g_prog)[i] = 0;
    if (i < 3) g_ticket[i] = 0;
}

// ---------------------------------------------------------------------------
// Fused persistent kernel. Blocks 0..31: recurrence chains (b,d) through all
// 3 layers. Blocks 32..147: gemm workers producing xg tiles from a ticket
// queue, gated on recurrence progress. All 148 CTAs co-resident (occ 1).
// ---------------------------------------------------------------------------
__global__ void __launch_bounds__(384, 1) mega(const float* __restrict__ xin,
                                               const float* __restrict__ Wi,
                                               const float* __restrict__ Wh,
                                               const float* __restrict__ bh,
                                               float* __restrict__ out) {
    const int tid = threadIdx.x;

    if (blockIdx.x < 32) {
        // =================== recurrence CTA: chain (b,d) ===================
        const int b = blockIdx.x & 15;
        const int d = blockIdx.x >> 4;
        const int c0 = tid & 127;
        const int gate = tid >> 7;  // 0=r, 1=z, 2=n

        __shared__ __align__(16) float h_s[H_];
        __shared__ float rr[H_];
        __shared__ float zz[H_];
        const ulonglong2* const hp = (const ulonglong2*)h_s;

        for (int l = 0; l < 3; l++) {
            float* __restrict__ Y = (l == 2) ? out : g_buf[l];
            const float* __restrict__ W = Wh + (size_t)(l * 2 + d) * H_ * G3;
            const float* __restrict__ xgb =
                g_xg[l & 1] + ((size_t)d * BT + (size_t)b * T_) * G3;

            ull w[64];
            {
                const float* Wc = W + tid;
#pragma unroll
                for (int j = 0; j < 64; j++)
                    w[j] = fpack2(Wc[(size_t)(2 * j) * G3],
                                  Wc[(size_t)(2 * j + 1) * G3]);
            }
            const float bias = bh[(size_t)(l * 2 + d) * G3 + tid];
            const float badd = (gate == 2) ? 0.0f : bias;

            if (tid < H_) h_s[tid] = 0.0f;

            const int sd = d ? -1 : 1;
            const long xstep = (long)sd * G3;
            const long ystep = (long)sd * DIM_;
            const float* xp = xgb + (d ? (size_t)(T_ - 1) * G3 : 0) + tid;
            float* yp = Y + (size_t)b * T_ * DIM_ + d * H_ + c0 +
                        (d ? (size_t)(T_ - 1) * DIM_ : 0);

            // Wait for the first xg chunk, then preload xv.
            if (tid == 0) {
                int tc0 = d ? (NCHUNK - 1) : 0;
                while (*(volatile int*)&g_tileflag[l][d][b * NCHUNK + tc0] < NNT)
                    __nanosleep(128);
                __threadfence();
            }
            __syncthreads();
            float xv = *xp + badd;
            xp += xstep;

            for (int c = 0; c < NCHUNK; c++) {
                // Wait one chunk ahead (covers the prefetch at step 127).
                if (tid == 0 && c + 1 < NCHUNK) {
                    int tcn = d ? (NCHUNK - 2 - c) : (c + 1);
                    while (*(volatile int*)&g_tileflag[l][d][b * NCHUNK + tcn] < NNT)
                        __nanosleep(128);
                    __threadfence();
                }
                __syncthreads();

#pragma unroll 1
                for (int t2 = 0; t2 < CHUNK; t2++) {
                    // Dot: h . Wh[:, tid]  (32 broadcast LDS.128, 64 FFMA2).
                    ull acc0 = 0, acc1 = 0;
#pragma unroll
                    for (int j = 0; j < 32; j++) {
                        ulonglong2 hv = hp[j];
                        acc0 = ffma2(w[2 * j], hv.x, acc0);
                        acc1 = ffma2(w[2 * j + 1], hv.y, acc1);
                    }
                    float2 lo = funpack(acc0), hi = funpack(acc1);
                    float dot = (lo.x + lo.y) + (hi.x + hi.y);

                    // Prefetch next step's xg (one-past-end stays in g_xg).
                    float nxv = *xp + badd;
                    xp += xstep;

                    float hold = 0.0f, dn = 0.0f;
                    if (gate == 0) {
                        rr[c0] = sigmoidf_fast(xv + dot);
                    } else if (gate == 1) {
                        zz[c0] = sigmoidf_fast(xv + dot);
                    } else {
                        dn = dot + bias;
                        hold = h_s[c0];
                    }
                    __syncthreads();  // r,z published

                    if (gate == 2) {
                        float r = rr[c0];
                        float z = zz[c0];
                        float n = tanhf_fast(fmaf(r, dn, xv));
                        float hnew = fmaf(z, hold - n, n);
                        h_s[c0] = hnew;
                        *yp = hnew;
                    }
                    __syncthreads();  // new h visible

                    xv = nxv;
                    yp += ystep;
                }

                // Publish progress (release: fence -> bar -> flag).
                __threadfence();
                __syncthreads();
                if (tid == 0) atomicExch(&g_prog[l][d][b], (c + 1) * CHUNK);
            }
            __syncthreads();
        }
    } else {
        // ======================= gemm worker CTA ==========================
        // xg[l][d][bt][c] = sum_k X[bt][k] * Wi[l][d][k][c]
        // BM=128, BN=96, BK=16, 384 threads, 8x4 micro-tile.
        __shared__ __align__(16) float As[16][128];
        __shared__ __align__(16) float Bs[16][96];
        __shared__ int sh_tk;

        const int ar = tid >> 1;             // A fill row (tid<256)
        const int akq = (tid & 1) * 8;       // A fill k-octet
        const int bk = tid / 24;             // B fill k-row 0..15
        const int bc = (tid % 24) * 4;       // B fill col
        const int ry = (tid / 24) * 8;       // micro rows
        const int cx = (tid % 24) * 4;       // micro cols

        for (int l = 0; l < 3; l++) {
            const float* __restrict__ X = (l == 0) ? xin : g_buf[l - 1];
            float* __restrict__ Cb = g_xg[l & 1];

            while (true) {
                if (tid == 0) sh_tk = atomicAdd(&g_ticket[l], 1);
                __syncthreads();
                int tk = sh_tk;
                if (tk >= TICKETS) break;

                // Decode ticket -> (tc, d, b, nt). Layer 0: ends-first tc
                // order (matches rnn consumption); layers 1-2: middle-out
                // (matches readiness).
                int i = tk >> 7;       // 0..31
                int rem = tk & 127;
                int tc;
                if (l == 0) {
                    tc = (i & 1) ? (31 - (i >> 1)) : (i >> 1);
                } else {
                    tc = (i & 1) ? (16 + (i >> 1)) : (15 - (i >> 1));
                }
                int d = rem >> 6;
                int b = (rem >> 2) & 15;
                int nt = rem & 3;
                int m = b * NCHUNK + tc;

                // Gate on upstream recurrence progress (acquire).
                if (l > 0) {
                    if (tid == 0) {
                        int needf = (tc + 1) * CHUNK;
                        int needb = T_ - tc * CHUNK;
                        while (*(volatile int*)&g_prog[l - 1][0][b] < needf)
                            __nanosleep(256);
                        while (*(volatile int*)&g_prog[l - 1][1][b] < needb)
                            __nanosleep(256);
                        __threadfence();
                    }
                    __syncthreads();
                }

                const int m0 = m * 128;
                const int n0 = nt * 96;
                const float* __restrict__ W =
                    Wi + (size_t)(l * 2 + d) * DIM_ * G3;
                float* __restrict__ C = Cb + (size_t)d * BT * G3;

                const float* Ap = X + (size_t)(m0 + ar) * DIM_ + akq;
                const float* Bp = W + (size_t)bk * G3 + n0 + bc;

                float acc[8][4];
#pragma unroll
                for (int ii = 0; ii < 8; ii++)
#pragma unroll
                    for (int jj = 0; jj < 4; jj++) acc[ii][jj] = 0.0f;

                float4 a0, a1, b0;
                if (tid < 256) {
                    a0 = *(const float4*)(Ap);
                    a1 = *(const float4*)(Ap + 4);
                }
                b0 = *(const float4*)(Bp);

#pragma unroll 1
                for (int k0 = 0; k0 < DIM_; k0 += 16) {
                    if (tid < 256) {
                        As[akq + 0][ar] = a0.x; As[akq + 1][ar] = a0.y;
                        As[akq + 2][ar] = a0.z; As[akq + 3][ar] = a0.w;
                        As[akq + 4][ar] = a1.x; As[akq + 5][ar] = a1.y;
                        As[akq + 6][ar] = a1.z; As[akq + 7][ar] = a1.w;
                    }
                    *(float4*)&Bs[bk][bc] = b0;
                    __syncthreads();

                    if (k0 + 16 < DIM_) {
                        if (tid < 256) {
                            a0 = *(const float4*)(Ap + k0 + 16);
                            a1 = *(const float4*)(Ap + k0 + 20);
                        }
                        b0 = *(const float4*)(Bp + (size_t)(k0 + 16) * G3);
                    }

#pragma unroll
                    for (int k = 0; k < 16; k++) {
                        float4 av0 = *(const float4*)&As[k][ry];
                        float4 av1 = *(const float4*)&As[k][ry + 4];
                        float4 bv = *(const float4*)&Bs[k][cx];
                        float a[8] = {av0.x, av0.y, av0.z, av0.w,
                                      av1.x, av1.y, av1.z, av1.w};
                        float bb2[4] = {bv.x, bv.y, bv.z, bv.w};
#pragma unroll
                        for (int ii = 0; ii < 8; ii++)
#pragma unroll
                            for (int jj = 0; jj < 4; jj++)
                                acc[ii][jj] = fmaf(a[ii], bb2[jj], acc[ii][jj]);
                    }
                    __syncthreads();
                }

#pragma unroll
                for (int ii = 0; ii < 8; ii++) {
                    float* crow = C + (size_t)(m0 + ry + ii) * G3 + n0 + cx;
                    *(float4*)crow =
                        make_float4(acc[ii][0], acc[ii][1], acc[ii][2], acc[ii][3]);
                }

                // Publish tile (release).
                __threadfence();
                __syncthreads();
                if (tid == 0) atomicAdd(&g_tileflag[l][d][m], 1);
            }
        }
    }
}

// ---------------------------------------------------------------------------
extern "C" void kernel_launch(void* const* d_in, const int* in_sizes, int n_in,
                              void* d_out, int out_size) {
    (void)in_sizes;
    (void)n_in;
    (void)out_size;
    const float* x = (const float*)d_in[0];    // [16,4096,256]
    const float* Wi = (const float*)d_in[1];   // [3,2,256,384]
    const float* Wh = (const float*)d_in[2];   // [3,2,128,384]
    const float* bh = (const float*)d_in[3];   // [3,2,384]
    float* out = (float*)d_out;                // [16,4096,256]

    init_sync<<<13, 256>>>();
    mega<<<148, 384>>>(x, Wi, Wh, bh, out);
}